// round 5
// baseline (speedup 1.0000x reference)
#include <cuda_runtime.h>
#include <cuda_bf16.h>
#include <math.h>

#define NU 100000
#define NR 50000
#define NE 600000
#define NL 200000
#define HD 128
#define OD 64

typedef unsigned long long u64;

// ---------------- f32x2 packed math ----------------
__device__ __forceinline__ u64 fma2(u64 a, u64 b, u64 c) {
    u64 d;
    asm("fma.rn.f32x2 %0, %1, %2, %3;" : "=l"(d) : "l"(a), "l"(b), "l"(c));
    return d;
}
__device__ __forceinline__ u64 pack2(float x, float y) {
    u64 d; asm("mov.b64 %0, {%1, %2};" : "=l"(d) : "f"(x), "f"(y)); return d;
}
__device__ __forceinline__ float2 unpack2(u64 v) {
    float2 r; asm("mov.b64 {%0, %1}, %2;" : "=f"(r.x), "=f"(r.y) : "l"(v)); return r;
}

// ---------------- scratch ----------------
__device__ __align__(16) float g_hu[(size_t)NU * HD];
__device__ __align__(16) float g_hr[(size_t)NR * HD];
__device__ __align__(16) float g_p1[(size_t)NR * HD];
__device__ __align__(16) float g_u1[(size_t)NU * HD];
__device__ __align__(16) float g_r1[(size_t)NR * HD];
__device__ __align__(16) float g_mean_u[(size_t)NU * HD]; // mu, then U2
__device__ __align__(16) float g_mean_r[(size_t)NR * HD]; // mr, then R2
__device__ __align__(16) float g_zu[(size_t)NU * OD];
__device__ __align__(16) float g_zr[(size_t)NR * OD];
__device__ __align__(16) float g_wt[147456];

__device__ int g_deg_r[NR];
__device__ int g_deg_u[NU];
__device__ int g_off_r[NR + 1];
__device__ int g_off_u[NU + 1];
__device__ int g_cur_r[NR];
__device__ int g_cur_u[NU];
__device__ int g_csr_r[NE];
__device__ int g_csr_u[NE];

#define WT_WU      0
#define WT_WREC    16384
#define WT_C1URWL  49152
#define WT_C1URWR  65536
#define WT_C1RUWL  81920
#define WT_C1RUWR  98304
#define WT_U2      114688   // [128][128]: cols 0-63 c2_ur_Wl^T, 64-127 c2_ru_Wr^T
#define WT_R2      131072   // [128][128]: cols 0-63 c2_ru_Wl^T, 64-127 c2_ur_Wr^T

// ---------------- CSR build ----------------
__global__ void zero_deg(int* __restrict__ deg_u, int* __restrict__ deg_r)
{
    int t = blockIdx.x * blockDim.x + threadIdx.x;
    if (t < NU) deg_u[t] = 0;
    if (t < NR) deg_r[t] = 0;
}

__global__ void count_kernel(const int* __restrict__ es, const int* __restrict__ ed,
                             int* __restrict__ deg_u, int* __restrict__ deg_r, int E)
{
    int t = blockIdx.x * blockDim.x + threadIdx.x;
    if (t < E) {
        atomicAdd(&deg_u[es[t]], 1);
        atomicAdd(&deg_r[ed[t]], 1);
    }
}

__global__ void scan2_kernel(const int* __restrict__ deg_r, int* __restrict__ off_r,
                             int* __restrict__ cur_r,
                             const int* __restrict__ deg_u, int* __restrict__ off_u,
                             int* __restrict__ cur_u)
{
    const int* deg; int* off; int* cur; int n;
    if (blockIdx.x == 0) { deg = deg_r; off = off_r; cur = cur_r; n = NR; }
    else                 { deg = deg_u; off = off_u; cur = cur_u; n = NU; }
    __shared__ int tmp[1024];
    int t = threadIdx.x;
    int chunk = (n + 1023) / 1024;
    int start = min(t * chunk, n);
    int end = min(start + chunk, n);
    int s = 0;
    for (int i = start; i < end; i++) s += deg[i];
    tmp[t] = s;
    __syncthreads();
    for (int d = 1; d < 1024; d <<= 1) {
        int v = (t >= d) ? tmp[t - d] : 0;
        __syncthreads();
        tmp[t] += v;
        __syncthreads();
    }
    int run = (t == 0) ? 0 : tmp[t - 1];
    for (int i = start; i < end; i++) {
        off[i] = run;
        cur[i] = run;
        run += deg[i];
    }
    if (end == n) off[n] = run;
}

__global__ void fill_kernel(const int* __restrict__ es, const int* __restrict__ ed,
                            int* __restrict__ cur_u, int* __restrict__ cur_r,
                            int* __restrict__ csr_u, int* __restrict__ csr_r, int E)
{
    int t = blockIdx.x * blockDim.x + threadIdx.x;
    if (t < E) {
        int s = es[t], d = ed[t];
        int pr = atomicAdd(&cur_r[d], 1);
        csr_r[pr] = s;
        int pu = atomicAdd(&cur_u[s], 1);
        csr_u[pu] = d;
    }
}

// ---------------- weight transpose ----------------
struct WtArgs {
    const float* src[10];
    int n[10];
    int k[10];
    int dstN[10];
    int coloff[10];
    int doff[10];
    int blk_off[11];
};

__global__ void wtrans_kernel(WtArgs a, float* __restrict__ dst)
{
    int b = blockIdx.x;
    int m = 0;
    while (b >= a.blk_off[m + 1]) m++;
    int idx = (b - a.blk_off[m]) * 256 + threadIdx.x;
    int N = a.n[m], K = a.k[m];
    if (idx < N * K) {
        int kk = idx / N, nn = idx - kk * N;
        dst[a.doff[m] + kk * a.dstN[m] + a.coloff[m] + nn] = a.src[m][nn * K + kk];
    }
}

// ---------------- gather-mean 128-dim, warp/node, unroll-4 ----------------
__global__ __launch_bounds__(256) void gather2_128(
    const float4* __restrict__ featR, const float4* __restrict__ featU,
    const int* __restrict__ off_r, const int* __restrict__ csr_r,
    const int* __restrict__ off_u, const int* __restrict__ csr_u,
    float4* __restrict__ outR, float4* __restrict__ outU)
{
    int warp = (blockIdx.x * blockDim.x + threadIdx.x) >> 5;
    int lane = threadIdx.x & 31;
    const float4* feat;
    const int* off;
    const int* csr;
    float4* outm;
    int node;
    if (warp < NR) {
        feat = featR; off = off_r; csr = csr_r; outm = outR; node = warp;
    } else if (warp < NR + NU) {
        feat = featU; off = off_u; csr = csr_u; outm = outU; node = warp - NR;
    } else return;
    int b = off[node], e = off[node + 1];
    float4 acc = make_float4(0.f, 0.f, 0.f, 0.f);
    int i = b;
    for (; i + 4 <= e; i += 4) {
        int n0 = csr[i], n1 = csr[i + 1], n2 = csr[i + 2], n3 = csr[i + 3];
        float4 v0 = feat[(size_t)n0 * 32 + lane];
        float4 v1 = feat[(size_t)n1 * 32 + lane];
        float4 v2 = feat[(size_t)n2 * 32 + lane];
        float4 v3 = feat[(size_t)n3 * 32 + lane];
        acc.x += v0.x + v1.x + v2.x + v3.x;
        acc.y += v0.y + v1.y + v2.y + v3.y;
        acc.z += v0.z + v1.z + v2.z + v3.z;
        acc.w += v0.w + v1.w + v2.w + v3.w;
    }
    for (; i < e; i++) {
        int nb = csr[i];
        float4 v = feat[(size_t)nb * 32 + lane];
        acc.x += v.x; acc.y += v.y; acc.z += v.z; acc.w += v.w;
    }
    float inv = 1.f / fmaxf((float)(e - b), 1.f);
    acc.x *= inv; acc.y *= inv; acc.z *= inv; acc.w *= inv;
    outm[(size_t)node * 32 + lane] = acc;
}

// ---------------- fused 64-dim gather + bias + root-term ----------------
__global__ __launch_bounds__(256) void gather2_64f(
    const float2* __restrict__ U2, const float2* __restrict__ R2,
    const float* __restrict__ bl_ur, const float* __restrict__ bl_ru,
    const int* __restrict__ off_r, const int* __restrict__ csr_r,
    const int* __restrict__ off_u, const int* __restrict__ csr_u,
    float2* __restrict__ zr, float2* __restrict__ zu)
{
    int warp = (blockIdx.x * blockDim.x + threadIdx.x) >> 5;
    int lane = threadIdx.x & 31;
    const float2* feat;
    const float2* selfp;
    const float2* bl;
    const int* off;
    const int* csr;
    float2* outp;
    int node;
    if (warp < NR) {
        node = warp;
        feat = U2; selfp = R2; bl = (const float2*)bl_ur;
        off = off_r; csr = csr_r; outp = zr;
    } else if (warp < NR + NU) {
        node = warp - NR;
        feat = R2; selfp = U2; bl = (const float2*)bl_ru;
        off = off_u; csr = csr_u; outp = zu;
    } else return;
    int b = off[node], e = off[node + 1];
    float2 acc = make_float2(0.f, 0.f);
    int i = b;
    for (; i + 4 <= e; i += 4) {
        int n0 = csr[i], n1 = csr[i + 1], n2 = csr[i + 2], n3 = csr[i + 3];
        float2 v0 = feat[(size_t)n0 * 64 + lane];
        float2 v1 = feat[(size_t)n1 * 64 + lane];
        float2 v2 = feat[(size_t)n2 * 64 + lane];
        float2 v3 = feat[(size_t)n3 * 64 + lane];
        acc.x += v0.x + v1.x + v2.x + v3.x;
        acc.y += v0.y + v1.y + v2.y + v3.y;
    }
    for (; i < e; i++) {
        int nb = csr[i];
        float2 v = feat[(size_t)nb * 64 + lane];
        acc.x += v.x; acc.y += v.y;
    }
    float inv = 1.f / fmaxf((float)(e - b), 1.f);
    float2 s = selfp[(size_t)node * 64 + 32 + lane];
    float2 bb = bl[lane];
    float2 o;
    o.x = acc.x * inv + bb.x + s.x;
    o.y = acc.y * inv + bb.y + s.y;
    outp[(size_t)node * 32 + lane] = o;
}

// ---------------- shared mainloop: acc += sA@sWl (+ sX@sWr) ----------------
template <int N, int K, bool DUAL>
__device__ __forceinline__ void mm_acc(
    const float* __restrict__ sA, const float* __restrict__ sX,
    const float* __restrict__ sWl, const float* __restrict__ sWr,
    int r0, int colbase, u64 acc[8][N / 64])
{
    constexpr int CPT = N / 32;
    constexpr int PAIRS = CPT / 2;
#pragma unroll 2
    for (int k0 = 0; k0 < K; k0 += 4) {
        float4 a4[8], x4[8];
#pragma unroll
        for (int i = 0; i < 8; i++) {
            a4[i] = *(const float4*)&sA[(r0 + i) * K + k0];
            if (DUAL) x4[i] = *(const float4*)&sX[(r0 + i) * K + k0];
        }
#pragma unroll
        for (int kk = 0; kk < 4; kk++) {
            u64 wl[PAIRS], wr[PAIRS];
            const float* wlp = &sWl[(k0 + kk) * N + colbase];
            if (CPT == 4) {
                float4 v = *(const float4*)wlp;
                wl[0] = pack2(v.x, v.y);
                if (PAIRS > 1) wl[1] = pack2(v.z, v.w);
            } else {
                float2 v = *(const float2*)wlp;
                wl[0] = pack2(v.x, v.y);
            }
            if (DUAL) {
                const float* wrp = &sWr[(k0 + kk) * N + colbase];
                if (CPT == 4) {
                    float4 v = *(const float4*)wrp;
                    wr[0] = pack2(v.x, v.y);
                    if (PAIRS > 1) wr[1] = pack2(v.z, v.w);
                } else {
                    float2 v = *(const float2*)wrp;
                    wr[0] = pack2(v.x, v.y);
                }
            }
#pragma unroll
            for (int i = 0; i < 8; i++) {
                float as = (kk == 0) ? a4[i].x : (kk == 1) ? a4[i].y :
                           (kk == 2) ? a4[i].z : a4[i].w;
                u64 a2 = pack2(as, as);
#pragma unroll
                for (int p = 0; p < PAIRS; p++) acc[i][p] = fma2(a2, wl[p], acc[i][p]);
                if (DUAL) {
                    float xs = (kk == 0) ? x4[i].x : (kk == 1) ? x4[i].y :
                               (kk == 2) ? x4[i].z : x4[i].w;
                    u64 x2 = pack2(xs, xs);
#pragma unroll
                    for (int p = 0; p < PAIRS; p++) acc[i][p] = fma2(x2, wr[p], acc[i][p]);
                }
            }
        }
    }
}

// ---------------- persistent GEMM ----------------
template <int N, int K, bool DUAL, bool ADDIN, bool HASB, bool RELU>
__global__ __launch_bounds__(256) void gemm_k(
    const float* __restrict__ A, const float* __restrict__ X,
    const float* __restrict__ Wlt, const float* __restrict__ Wrt,
    const float* __restrict__ bl, const float* __restrict__ ADDP,
    float* __restrict__ Y, int M)
{
    constexpr int CPT = N / 32;
    constexpr int PAIRS = CPT / 2;
    extern __shared__ float sm[];
    float* sWl = sm;
    float* sWr = sm + K * N;
    float* sA  = sm + (DUAL ? 2 : 1) * K * N;
    float* sX  = sA + 64 * K;

    const int tid = threadIdx.x;

    {
        const float4* w4 = (const float4*)Wlt;
        float4* s4 = (float4*)sWl;
        for (int i = tid; i < K * N / 4; i += 256) s4[i] = w4[i];
        if (DUAL) {
            const float4* v4 = (const float4*)Wrt;
            float4* t4 = (float4*)sWr;
            for (int i = tid; i < K * N / 4; i += 256) t4[i] = v4[i];
        }
    }

    const int lane = tid & 31;
    const int w = tid >> 5;
    const int r0 = w * 8;
    const int colbase = lane * CPT;

    float bv[CPT];
#pragma unroll
    for (int j = 0; j < CPT; j++) bv[j] = HASB ? bl[colbase + j] : 0.f;

    const int ntiles = (M + 63) >> 6;
    for (int tile = blockIdx.x; tile < ntiles; tile += gridDim.x) {
        const int row0 = tile << 6;
        __syncthreads();
        {
            int lim = min(64, M - row0) * (K / 4);
            const float4* A4 = (const float4*)(A + (size_t)row0 * K);
            float4* sA4 = (float4*)sA;
            const float4* X4 = DUAL ? (const float4*)(X + (size_t)row0 * K) : nullptr;
            float4* sX4 = (float4*)sX;
            for (int i = tid; i < 64 * K / 4; i += 256) {
                float4 v = (i < lim) ? A4[i] : make_float4(0.f, 0.f, 0.f, 0.f);
                sA4[i] = v;
                if (DUAL) {
                    float4 u = (i < lim) ? X4[i] : make_float4(0.f, 0.f, 0.f, 0.f);
                    sX4[i] = u;
                }
            }
        }
        __syncthreads();

        u64 acc[8][PAIRS];
#pragma unroll
        for (int i = 0; i < 8; i++)
#pragma unroll
            for (int p = 0; p < PAIRS; p++) acc[i][p] = 0ull;

        mm_acc<N, K, DUAL>(sA, sX, sWl, sWr, r0, colbase, acc);

#pragma unroll
        for (int i = 0; i < 8; i++) {
            int row = row0 + r0 + i;
            if (row < M) {
                float o[CPT];
#pragma unroll
                for (int p = 0; p < PAIRS; p++) {
                    float2 v = unpack2(acc[i][p]);
                    o[2 * p] = v.x + bv[2 * p];
                    o[2 * p + 1] = v.y + bv[2 * p + 1];
                }
                if (ADDIN) {
                    const float* ap = &ADDP[(size_t)row * N + colbase];
                    if (CPT == 4) {
                        float4 v = *(const float4*)ap;
                        o[0] += v.x; o[1] += v.y; o[2] += v.z; o[3] += v.w;
                    } else {
                        float2 v = *(const float2*)ap;
                        o[0] += v.x; o[1] += v.y;
                    }
                }
                if (RELU) {
#pragma unroll
                    for (int j = 0; j < CPT; j++) o[j] = fmaxf(o[j], 0.f);
                }
                float* yp = &Y[(size_t)row * N + colbase];
                if (CPT == 4) *(float4*)yp = make_float4(o[0], o[1], o[2], o[3]);
                else          *(float2*)yp = make_float2(o[0], o[1]);
            }
        }
    }
}

// ---------------- fused u1 + U2 kernel ----------------
// pass1: u1 = relu(hu@W1 + bl + mu)  -> gmem u1, smem su1
// pass2: U2 = u1@W2                  -> gmem U2
// smem: W1 64K + W2 64K + sA 32K + su1 32K = 192K
__global__ __launch_bounds__(256) void gemm_fused_u1U2(
    const float* __restrict__ HU, const float* __restrict__ W1t,
    const float* __restrict__ W2t, const float* __restrict__ bl,
    const float* __restrict__ MU, float* __restrict__ U1out,
    float* __restrict__ U2out, int M)
{
    extern __shared__ float sm[];
    float* sW1 = sm;                  // 128*128
    float* sW2 = sm + 16384;          // 128*128
    float* sA  = sm + 32768;          // 64*128
    float* su1 = sm + 40960;          // 64*128

    const int tid = threadIdx.x;
    {
        const float4* a4 = (const float4*)W1t;
        const float4* b4 = (const float4*)W2t;
        float4* s14 = (float4*)sW1;
        float4* s24 = (float4*)sW2;
        for (int i = tid; i < 16384 / 4; i += 256) {
            s14[i] = a4[i];
            s24[i] = b4[i];
        }
    }

    const int lane = tid & 31;
    const int w = tid >> 5;
    const int r0 = w * 8;
    const int colbase = lane * 4;

    float bv[4];
#pragma unroll
    for (int j = 0; j < 4; j++) bv[j] = bl[colbase + j];

    const int ntiles = (M + 63) >> 6;
    for (int tile = blockIdx.x; tile < ntiles; tile += gridDim.x) {
        const int row0 = tile << 6;
        __syncthreads();
        {
            int lim = min(64, M - row0) * 32;
            const float4* A4 = (const float4*)(HU + (size_t)row0 * 128);
            float4* sA4 = (float4*)sA;
            for (int i = tid; i < 64 * 32; i += 256)
                sA4[i] = (i < lim) ? A4[i] : make_float4(0.f, 0.f, 0.f, 0.f);
        }
        __syncthreads();

        // ---- pass 1 ----
        u64 acc[8][2];
#pragma unroll
        for (int i = 0; i < 8; i++) { acc[i][0] = 0ull; acc[i][1] = 0ull; }
        mm_acc<128, 128, false>(sA, nullptr, sW1, nullptr, r0, colbase, acc);

#pragma unroll
        for (int i = 0; i < 8; i++) {
            int row = row0 + r0 + i;
            float o[4];
            float2 v0 = unpack2(acc[i][0]);
            float2 v1 = unpack2(acc[i][1]);
            o[0] = v0.x + bv[0]; o[1] = v0.y + bv[1];
            o[2] = v1.x + bv[2]; o[3] = v1.y + bv[3];
            if (row < M) {
                const float4 vm = *(const float4*)&MU[(size_t)row * 128 + colbase];
                o[0] += vm.x; o[1] += vm.y; o[2] += vm.z; o[3] += vm.w;
#pragma unroll
                for (int j = 0; j < 4; j++) o[j] = fmaxf(o[j], 0.f);
                *(float4*)&U1out[(size_t)row * 128 + colbase] =
                    make_float4(o[0], o[1], o[2], o[3]);
            } else {
                o[0] = o[1] = o[2] = o[3] = 0.f;
            }
            *(float4*)&su1[(r0 + i) * 128 + colbase] =
                make_float4(o[0], o[1], o[2], o[3]);
        }
        __syncthreads();

        // ---- pass 2 ----
#pragma unroll
        for (int i = 0; i < 8; i++) { acc[i][0] = 0ull; acc[i][1] = 0ull; }
        mm_acc<128, 128, false>(su1, nullptr, sW2, nullptr, r0, colbase, acc);

#pragma unroll
        for (int i = 0; i < 8; i++) {
            int row = row0 + r0 + i;
            if (row < M) {
                float2 v0 = unpack2(acc[i][0]);
                float2 v1 = unpack2(acc[i][1]);
                *(float4*)&U2out[(size_t)row * 128 + colbase] =
                    make_float4(v0.x, v0.y, v1.x, v1.y);
            }
        }
    }
}

// ---------------- decoder ----------------
__global__ __launch_bounds__(256) void decode_kernel(
    const float2* __restrict__ zu, const float2* __restrict__ zr,
    const int* __restrict__ ls, const int* __restrict__ ld,
    float* __restrict__ out, int L)
{
    int warp = (blockIdx.x * blockDim.x + threadIdx.x) >> 5;
    int lane = threadIdx.x & 31;
    if (warp >= L) return;
    int s = ls[warp], d = ld[warp];
    float2 a = zu[(size_t)s * 32 + lane];
    float2 b = zr[(size_t)d * 32 + lane];
    float dot = a.x * b.x + a.y * b.y;
    float na = a.x * a.x + a.y * a.y;
    float nb = b.x * b.x + b.y * b.y;
#pragma unroll
    for (int o = 16; o; o >>= 1) {
        dot += __shfl_xor_sync(0xffffffffu, dot, o);
        na  += __shfl_xor_sync(0xffffffffu, na, o);
        nb  += __shfl_xor_sync(0xffffffffu, nb, o);
    }
    if (lane == 0)
        out[warp] = dot / (fmaxf(sqrtf(na), 1e-12f) * fmaxf(sqrtf(nb), 1e-12f));
}

// ---------------- host launch ----------------
extern "C" void kernel_launch(void* const* d_in, const int* in_sizes, int n_in,
                              void* d_out, int out_size)
{
    const float* x_user   = (const float*)d_in[0];
    const float* x_recipe = (const float*)d_in[1];
    const int* edge_src   = (const int*)d_in[2];
    const int* edge_dst   = (const int*)d_in[3];
    const int* lbl_src    = (const int*)d_in[4];
    const int* lbl_dst    = (const int*)d_in[5];
    const float* Wu   = (const float*)d_in[6];
    const float* bu   = (const float*)d_in[7];
    const float* Wrec = (const float*)d_in[8];
    const float* brec = (const float*)d_in[9];
    const float* c1_ur_Wl = (const float*)d_in[10];
    const float* c1_ur_bl = (const float*)d_in[11];
    const float* c1_ur_Wr = (const float*)d_in[12];
    const float* c1_ru_Wl = (const float*)d_in[13];
    const float* c1_ru_bl = (const float*)d_in[14];
    const float* c1_ru_Wr = (const float*)d_in[15];
    const float* c2_ur_Wl = (const float*)d_in[16];
    const float* c2_ur_bl = (const float*)d_in[17];
    const float* c2_ur_Wr = (const float*)d_in[18];
    const float* c2_ru_Wl = (const float*)d_in[19];
    const float* c2_ru_bl = (const float*)d_in[20];
    const float* c2_ru_Wr = (const float*)d_in[21];
    float* out = (float*)d_out;

    float *hu, *hr, *p1, *u1, *r1, *mu, *mr, *zu, *zr, *wt;
    int *deg_r, *deg_u, *off_r, *off_u, *cur_r, *cur_u, *csr_r, *csr_u;
    cudaGetSymbolAddress((void**)&hu, g_hu);
    cudaGetSymbolAddress((void**)&hr, g_hr);
    cudaGetSymbolAddress((void**)&p1, g_p1);
    cudaGetSymbolAddress((void**)&u1, g_u1);
    cudaGetSymbolAddress((void**)&r1, g_r1);
    cudaGetSymbolAddress((void**)&mu, g_mean_u);
    cudaGetSymbolAddress((void**)&mr, g_mean_r);
    cudaGetSymbolAddress((void**)&zu, g_zu);
    cudaGetSymbolAddress((void**)&zr, g_zr);
    cudaGetSymbolAddress((void**)&wt, g_wt);
    cudaGetSymbolAddress((void**)&deg_r, g_deg_r);
    cudaGetSymbolAddress((void**)&deg_u, g_deg_u);
    cudaGetSymbolAddress((void**)&off_r, g_off_r);
    cudaGetSymbolAddress((void**)&off_u, g_off_u);
    cudaGetSymbolAddress((void**)&cur_r, g_cur_r);
    cudaGetSymbolAddress((void**)&cur_u, g_cur_u);
    cudaGetSymbolAddress((void**)&csr_r, g_csr_r);
    cudaGetSymbolAddress((void**)&csr_u, g_csr_u);

    static cudaStream_t side = nullptr, s2 = nullptr;
    static cudaEvent_t evF = nullptr, evJ = nullptr, evG = nullptr, evA = nullptr;
    if (side == nullptr) {
        cudaStreamCreateWithFlags(&side, cudaStreamNonBlocking);
        cudaStreamCreateWithFlags(&s2, cudaStreamNonBlocking);
        cudaEventCreateWithFlags(&evF, cudaEventDisableTiming);
        cudaEventCreateWithFlags(&evJ, cudaEventDisableTiming);
        cudaEventCreateWithFlags(&evG, cudaEventDisableTiming);
        cudaEventCreateWithFlags(&evA, cudaEventDisableTiming);
    }

    const int S_P128 = (128 * 128 + 64 * 128) * 4;           // 98304
    const int S_P256 = (256 * 128 + 64 * 256) * 4;           // 196608
    const int S_D128 = (2 * 128 * 128 + 2 * 64 * 128) * 4;   // 196608
    const int S_FUSE = (2 * 128 * 128 + 2 * 64 * 128) * 4;   // 196608

    cudaFuncSetAttribute((gemm_k<128, 128, false, false, true,  false>),
                         cudaFuncAttributeMaxDynamicSharedMemorySize, S_P128);
    cudaFuncSetAttribute((gemm_k<128, 256, false, false, true,  false>),
                         cudaFuncAttributeMaxDynamicSharedMemorySize, S_P256);
    cudaFuncSetAttribute((gemm_k<128, 128, false, false, false, false>),
                         cudaFuncAttributeMaxDynamicSharedMemorySize, S_P128);
    cudaFuncSetAttribute((gemm_k<128, 128, true,  false, true,  true>),
                         cudaFuncAttributeMaxDynamicSharedMemorySize, S_D128);
    cudaFuncSetAttribute(gemm_fused_u1U2,
                         cudaFuncAttributeMaxDynamicSharedMemorySize, S_FUSE);

    // ---- fork: CSR on side stream (kernels: zero(1), count(2), scan(3), fill(4)) ----
    cudaEventRecord(evF, 0);
    cudaStreamWaitEvent(side, evF, 0);
    zero_deg<<<(NU + 255) / 256, 256, 0, side>>>(deg_u, deg_r);
    count_kernel<<<(NE + 255) / 256, 256, 0, side>>>(edge_src, edge_dst, deg_u, deg_r, NE);
    scan2_kernel<<<2, 1024, 0, side>>>(deg_r, off_r, cur_r, deg_u, off_u, cur_u);
    fill_kernel<<<(NE + 255) / 256, 256, 0, side>>>(edge_src, edge_dst, cur_u, cur_r,
                                                    csr_u, csr_r, NE);
    cudaEventRecord(evJ, side);

    // ---- main: wtrans(5), hu(6 <- ncu capture lands here) ----
    {
        WtArgs a;
        const float* srcs[10] = {Wu, Wrec, c1_ur_Wl, c1_ur_Wr, c1_ru_Wl, c1_ru_Wr,
                                 c2_ur_Wl, c2_ru_Wr, c2_ru_Wl, c2_ur_Wr};
        int ns[10]   = {128, 128, 128, 128, 128, 128, 64, 64, 64, 64};
        int ks[10]   = {128, 256, 128, 128, 128, 128, 128, 128, 128, 128};
        int dn[10]   = {128, 128, 128, 128, 128, 128, 128, 128, 128, 128};
        int co[10]   = {0, 0, 0, 0, 0, 0, 0, 64, 0, 64};
        int doffs[10] = {WT_WU, WT_WREC, WT_C1URWL, WT_C1URWR, WT_C1RUWL, WT_C1RUWR,
                         WT_U2, WT_U2, WT_R2, WT_R2};
        int boff = 0;
        for (int m = 0; m < 10; m++) {
            a.src[m] = srcs[m]; a.n[m] = ns[m]; a.k[m] = ks[m];
            a.dstN[m] = dn[m]; a.coloff[m] = co[m]; a.doff[m] = doffs[m];
            a.blk_off[m] = boff;
            boff += (ns[m] * ks[m] + 255) / 256;
        }
        a.blk_off[10] = boff;
        wtrans_kernel<<<boff, 256>>>(a, wt);
    }

    gemm_k<128, 128, false, false, true, false><<<296, 256, S_P128>>>(
        x_user, nullptr, wt + WT_WU, nullptr, bu, nullptr, hu, NU);
    gemm_k<128, 256, false, false, true, false><<<148, 256, S_P256>>>(
        x_recipe, nullptr, wt + WT_WREC, nullptr, brec, nullptr, hr, NR);
    gemm_k<128, 128, false, false, false, false><<<296, 256, S_P128>>>(
        hr, nullptr, wt + WT_C1RUWL, nullptr, nullptr, nullptr, p1, NR);

    // ---- join CSR, conv1 gather ----
    cudaStreamWaitEvent(0, evJ, 0);
    const int GW = ((NR + NU) * 32 + 255) / 256;
    gather2_128<<<GW, 256>>>((const float4*)hu, (const float4*)p1,
                             off_r, csr_r, off_u, csr_u,
                             (float4*)mr, (float4*)mu);
    cudaEventRecord(evG, 0);

    // ---- conv1 GEMMs concurrently: r1-dual on s2, u1+U2 fused on main ----
    cudaStreamWaitEvent(s2, evG, 0);
    gemm_k<128, 128, true, false, true, true><<<148, 256, S_D128, s2>>>(
        mr, hr, wt + WT_C1URWL, wt + WT_C1URWR, c1_ur_bl, nullptr, r1, NR);
    cudaEventRecord(evA, s2);

    gemm_fused_u1U2<<<148, 256, S_FUSE>>>(
        hu, wt + WT_C1RUWR, wt + WT_U2, c1_ru_bl, mu, u1, mu /*U2 in-place*/, NU);

    // ---- R2 after r1; then fused conv2 gather ----
    cudaStreamWaitEvent(0, evA, 0);
    gemm_k<128, 128, false, false, false, false><<<296, 256, S_P128>>>(
        r1, nullptr, wt + WT_R2, nullptr, nullptr, nullptr, mr, NR);
    gather2_64f<<<GW, 256>>>((const float2*)mu, (const float2*)mr,
                             c2_ur_bl, c2_ru_bl,
                             off_r, csr_r, off_u, csr_u,
                             (float2*)zr, (float2*)zu);

    // ---- decoder ----
    decode_kernel<<<(NL * 32 + 255) / 256, 256>>>(
        (const float2*)zu, (const float2*)zr, lbl_src, lbl_dst, out, NL);
}